// round 1
// baseline (speedup 1.0000x reference)
#include <cuda_runtime.h>
#include <math.h>

#define N_NODES 50000
#define DK 128          // hidden/input feature dim
#define DOUT2 64        // final output dim
#define BN_EPS 1e-5f

// ---------------- scratch (static device allocations, allowed) ----------------
__device__ float g_agg[N_NODES * DK];   // aggregated neighbor features
__device__ float g_h[N_NODES * DK];     // pre-BN hidden
__device__ float g_x1[N_NODES * DK];    // layer activations (reused in place)
__device__ float g_stats[2 * DK];       // [0:128) colsum, [128:256) colsumsq
__device__ float g_ss[2 * DK];          // [0:128) scale, [128:256) shift
__device__ int   g_is64;                // edge_index dtype flag

// ---------------- utility kernels ----------------
__global__ void zero_kernel(float4* p, int n4) {
    int i = blockIdx.x * blockDim.x + threadIdx.x;
    if (i < n4) p[i] = make_float4(0.f, 0.f, 0.f, 0.f);
}

// Detect whether edge_index buffer is int64 or int32.
// If int64 (values < 50000), every odd 32-bit word is zero.
__global__ void detect_kernel(const int* __restrict__ ei32) {
    __shared__ int any;
    if (threadIdx.x == 0) any = 0;
    __syncthreads();
    int idx = 1 + 2 * threadIdx.x;   // odd words among first 256 ints
    if (ei32[idx] != 0) atomicOr(&any, 1);
    __syncthreads();
    if (threadIdx.x == 0) g_is64 = (any == 0) ? 1 : 0;
}

// ---------------- edge scatter: agg[dst] += x[src] ----------------
// one warp per edge, one float4 vector-red per lane (32 lanes * 4 = 128 feats)
__global__ void scatter_kernel(const float* __restrict__ x,
                               const void* __restrict__ eiv,
                               int E, float* __restrict__ agg) {
    int gw   = (blockIdx.x * blockDim.x + threadIdx.x) >> 5;
    int lane = threadIdx.x & 31;
    if (gw >= E) return;
    long long s, d;
    if (g_is64) {
        const long long* ei = (const long long*)eiv;
        s = ei[gw]; d = ei[E + gw];
    } else {
        const int* ei = (const int*)eiv;
        s = ei[gw]; d = ei[E + gw];
    }
    if ((unsigned long long)s >= N_NODES || (unsigned long long)d >= N_NODES) return;
    float4 v = *(const float4*)(x + (size_t)s * DK + lane * 4);
    float* p = agg + (size_t)d * DK + lane * 4;
    asm volatile("red.global.add.v4.f32 [%0], {%1, %2, %3, %4};"
                 :: "l"(p), "f"(v.x), "f"(v.y), "f"(v.z), "f"(v.w)
                 : "memory");
}

// ---------------- fused GEMM: out = agg @ Wl + x @ Wr + b (+ column stats) ----
// Block: 64 rows x DOUT cols; weights + row tiles staged in smem.
template<int DOUT>
__global__ void gemm_kernel(const float* __restrict__ A,  // agg  [nrows,128]
                            const float* __restrict__ X,  // self [nrows,128]
                            const float* __restrict__ Wl, // [128,DOUT]
                            const float* __restrict__ Wr, // [128,DOUT]
                            const float* __restrict__ bias,
                            float* __restrict__ out, int nrows,
                            float* __restrict__ stats, int doStats) {
    constexpr int K    = 128;
    constexpr int ROWS = 64;
    constexpr int CGN  = DOUT / 8;      // col groups of 8
    constexpr int TY   = 256 / CGN;     // row groups
    constexpr int RPT  = ROWS / TY;     // rows per thread
    constexpr int WLD  = DOUT + 4;      // padded W row stride
    constexpr int RLD  = 132;           // padded row-tile stride

    extern __shared__ float sm[];
    float* sWl = sm;                      // K*WLD
    float* sWr = sWl + K * WLD;           // K*WLD
    float* sA  = sWr + K * WLD;           // ROWS*RLD
    float* sX  = sA + ROWS * RLD;         // ROWS*RLD

    int t = threadIdx.x;
    int row0 = blockIdx.x * ROWS;

    // load weights
    for (int i = t; i < K * (DOUT / 4); i += 256) {
        int k = i / (DOUT / 4);
        int c = (i % (DOUT / 4)) * 4;
        *(float4*)&sWl[k * WLD + c] = *(const float4*)&Wl[k * DOUT + c];
        *(float4*)&sWr[k * WLD + c] = *(const float4*)&Wr[k * DOUT + c];
    }
    // load row tiles (agg + self), zero-padded past nrows
    for (int i = t; i < ROWS * (K / 4); i += 256) {
        int r = i / (K / 4);
        int c = (i % (K / 4)) * 4;
        int gr = row0 + r;
        float4 va = make_float4(0.f, 0.f, 0.f, 0.f), vx = va;
        if (gr < nrows) {
            va = *(const float4*)&A[(size_t)gr * K + c];
            vx = *(const float4*)&X[(size_t)gr * K + c];
        }
        *(float4*)&sA[r * RLD + c] = va;
        *(float4*)&sX[r * RLD + c] = vx;
    }
    __syncthreads();

    int cg = t % CGN;
    int ty = t / CGN;

    float acc[RPT][8];
#pragma unroll
    for (int i = 0; i < RPT; i++)
#pragma unroll
        for (int j = 0; j < 8; j++) acc[i][j] = 0.f;

#pragma unroll 4
    for (int k = 0; k < K; k++) {
        float4 wl0 = *(float4*)&sWl[k * WLD + cg * 8];
        float4 wl1 = *(float4*)&sWl[k * WLD + cg * 8 + 4];
        float4 wr0 = *(float4*)&sWr[k * WLD + cg * 8];
        float4 wr1 = *(float4*)&sWr[k * WLD + cg * 8 + 4];
#pragma unroll
        for (int i = 0; i < RPT; i++) {
            float a  = sA[(ty * RPT + i) * RLD + k];
            float xx = sX[(ty * RPT + i) * RLD + k];
            acc[i][0] += a * wl0.x + xx * wr0.x;
            acc[i][1] += a * wl0.y + xx * wr0.y;
            acc[i][2] += a * wl0.z + xx * wr0.z;
            acc[i][3] += a * wl0.w + xx * wr0.w;
            acc[i][4] += a * wl1.x + xx * wr1.x;
            acc[i][5] += a * wl1.y + xx * wr1.y;
            acc[i][6] += a * wl1.z + xx * wr1.z;
            acc[i][7] += a * wl1.w + xx * wr1.w;
        }
    }

    float bl[8];
#pragma unroll
    for (int j = 0; j < 8; j++) bl[j] = bias[cg * 8 + j];

    float ps[8], pq[8];
#pragma unroll
    for (int j = 0; j < 8; j++) { ps[j] = 0.f; pq[j] = 0.f; }

#pragma unroll
    for (int i = 0; i < RPT; i++) {
        int gr = row0 + ty * RPT + i;
        float v[8];
#pragma unroll
        for (int j = 0; j < 8; j++) v[j] = acc[i][j] + bl[j];
        if (gr < nrows) {
#pragma unroll
            for (int j = 0; j < 8; j++) { ps[j] += v[j]; pq[j] += v[j] * v[j]; }
            float4 o0 = make_float4(v[0], v[1], v[2], v[3]);
            float4 o1 = make_float4(v[4], v[5], v[6], v[7]);
            *(float4*)&out[(size_t)gr * DOUT + cg * 8]     = o0;
            *(float4*)&out[(size_t)gr * DOUT + cg * 8 + 4] = o1;
        }
    }

    if (doStats) {
        __syncthreads();           // done with sA contents
        float* red = sA;           // 256*16 floats fits in ROWS*RLD
#pragma unroll
        for (int j = 0; j < 8; j++) {
            red[t * 16 + j]     = ps[j];
            red[t * 16 + 8 + j] = pq[j];
        }
        __syncthreads();
        if (t < DOUT) {
            int jcg = t / 8, jj = t % 8;
            float s = 0.f, q = 0.f;
            for (int y = 0; y < TY; y++) {
                int tt = y * CGN + jcg;
                s += red[tt * 16 + jj];
                q += red[tt * 16 + 8 + jj];
            }
            atomicAdd(&stats[t], s);
            atomicAdd(&stats[DK + t], q);
        }
    }
}

// ---------------- BN finalize ----------------
__global__ void finalize_kernel(const float* __restrict__ stats,
                                const float* __restrict__ g,
                                const float* __restrict__ be,
                                float* __restrict__ ss, float invn) {
    int c = threadIdx.x;
    if (c < DK) {
        float mu  = stats[c] * invn;
        float var = stats[DK + c] * invn - mu * mu;
        float rs  = rsqrtf(var + BN_EPS);
        float s   = g[c] * rs;
        ss[c]      = s;
        ss[DK + c] = be[c] - mu * s;
    }
}

// ---------------- BN apply + exact GELU ----------------
__device__ __forceinline__ float gelu_exact(float v) {
    return 0.5f * v * (1.0f + erff(v * 0.70710678118654752f));
}

__global__ void bn_gelu_kernel(const float* __restrict__ h,
                               const float* __restrict__ ss,
                               float* __restrict__ out, int n4) {
    int i = blockIdx.x * blockDim.x + threadIdx.x;
    if (i >= n4) return;
    int c4 = i & (DK / 4 - 1);   // float4 column index within 128-wide row
    float4 v  = ((const float4*)h)[i];
    float4 sc = ((const float4*)ss)[c4];
    float4 sh = ((const float4*)(ss + DK))[c4];
    v.x = gelu_exact(v.x * sc.x + sh.x);
    v.y = gelu_exact(v.y * sc.y + sh.y);
    v.z = gelu_exact(v.z * sc.z + sh.z);
    v.w = gelu_exact(v.w * sc.w + sh.w);
    ((float4*)out)[i] = v;
}

// ---------------- launch ----------------
extern "C" void kernel_launch(void* const* d_in, const int* in_sizes, int n_in,
                              void* d_out, int out_size) {
    const float* x   = (const float*)d_in[0];
    const void*  ei  = d_in[1];
    const float* W0l = (const float*)d_in[2];
    const float* W0r = (const float*)d_in[3];
    const float* b0  = (const float*)d_in[4];
    const float* g0  = (const float*)d_in[5];
    const float* be0 = (const float*)d_in[6];
    const float* W1l = (const float*)d_in[7];
    const float* W1r = (const float*)d_in[8];
    const float* b1  = (const float*)d_in[9];
    const float* g1  = (const float*)d_in[10];
    const float* be1 = (const float*)d_in[11];
    const float* W2l = (const float*)d_in[12];
    const float* W2r = (const float*)d_in[13];
    const float* b2  = (const float*)d_in[14];
    float* out = (float*)d_out;

    int E = in_sizes[1] / 2;

    void* p;
    cudaGetSymbolAddress(&p, g_agg);   float* agg   = (float*)p;
    cudaGetSymbolAddress(&p, g_h);     float* h     = (float*)p;
    cudaGetSymbolAddress(&p, g_x1);    float* x1    = (float*)p;
    cudaGetSymbolAddress(&p, g_stats); float* stats = (float*)p;
    cudaGetSymbolAddress(&p, g_ss);    float* ss    = (float*)p;

    const int smem128 = (128 * (DK + 4) * 2 + 64 * 132 * 2) * 4;
    const int smem64  = (128 * (DOUT2 + 4) * 2 + 64 * 132 * 2) * 4;
    cudaFuncSetAttribute(gemm_kernel<DK>,    cudaFuncAttributeMaxDynamicSharedMemorySize, smem128);
    cudaFuncSetAttribute(gemm_kernel<DOUT2>, cudaFuncAttributeMaxDynamicSharedMemorySize, smem64);

    int zb      = (N_NODES * DK / 4 + 255) / 256;
    int sbl     = (E * 32 + 255) / 256;
    int gblocks = (N_NODES + 63) / 64;
    int n4      = N_NODES * DK / 4;
    int bgb     = (n4 + 255) / 256;
    float invn  = 1.0f / (float)N_NODES;

    detect_kernel<<<1, 128>>>((const int*)ei);

    // ---- layer 0 ----
    zero_kernel<<<zb, 256>>>((float4*)agg, N_NODES * DK / 4);
    zero_kernel<<<1, 64>>>((float4*)stats, 2 * DK / 4);
    scatter_kernel<<<sbl, 256>>>(x, ei, E, agg);
    gemm_kernel<DK><<<gblocks, 256, smem128>>>(agg, x, W0l, W0r, b0, h, N_NODES, stats, 1);
    finalize_kernel<<<1, 128>>>(stats, g0, be0, ss, invn);
    bn_gelu_kernel<<<bgb, 256>>>(h, ss, x1, n4);

    // ---- layer 1 ----
    zero_kernel<<<zb, 256>>>((float4*)agg, N_NODES * DK / 4);
    zero_kernel<<<1, 64>>>((float4*)stats, 2 * DK / 4);
    scatter_kernel<<<sbl, 256>>>(x1, ei, E, agg);
    gemm_kernel<DK><<<gblocks, 256, smem128>>>(agg, x1, W1l, W1r, b1, h, N_NODES, stats, 1);
    finalize_kernel<<<1, 128>>>(stats, g1, be1, ss, invn);
    bn_gelu_kernel<<<bgb, 256>>>(h, ss, x1, n4);   // in place: reads h, writes x1

    // ---- layer 2 (no BN/GELU) ----
    zero_kernel<<<zb, 256>>>((float4*)agg, N_NODES * DK / 4);
    scatter_kernel<<<sbl, 256>>>(x1, ei, E, agg);
    gemm_kernel<DOUT2><<<gblocks, 256, smem64>>>(agg, x1, W2l, W2r, b2, out, N_NODES, stats, 0);
}

// round 3
// speedup vs baseline: 1.6745x; 1.6745x over previous
#include <cuda_runtime.h>
#include <math.h>
#include <stdint.h>

#define N_NODES 50000
#define DK 128          // hidden/input feature dim
#define DOUT2 64        // final output dim
#define BN_EPS 1e-5f

// ---------------- scratch ----------------
__device__ float g_agg[N_NODES * DK];
__device__ float g_h[N_NODES * DK];
__device__ float g_x1[N_NODES * DK];
__device__ float g_stats[2 * DK];
__device__ float g_ss[2 * DK];
__device__ int   g_is64;

// ---------------- helpers ----------------
__device__ __forceinline__ uint32_t f2tf(float f) {
    uint32_t r; asm("cvt.rna.tf32.f32 %0, %1;" : "=r"(r) : "f"(f)); return r;
}

__device__ __forceinline__ void mma_tf32(float* c, const uint32_t* a,
                                         uint32_t b0, uint32_t b1) {
    asm volatile(
        "mma.sync.aligned.m16n8k8.row.col.f32.tf32.tf32.f32 "
        "{%0,%1,%2,%3}, {%4,%5,%6,%7}, {%8,%9}, {%0,%1,%2,%3};"
        : "+f"(c[0]), "+f"(c[1]), "+f"(c[2]), "+f"(c[3])
        : "r"(a[0]), "r"(a[1]), "r"(a[2]), "r"(a[3]), "r"(b0), "r"(b1));
}

// ---------------- utility kernels ----------------
__global__ void zero_kernel(float4* p, int n4) {
    int i = blockIdx.x * blockDim.x + threadIdx.x;
    if (i < n4) p[i] = make_float4(0.f, 0.f, 0.f, 0.f);
}

__global__ void detect_kernel(const int* __restrict__ ei32) {
    __shared__ int any;
    if (threadIdx.x == 0) any = 0;
    __syncthreads();
    int idx = 1 + 2 * threadIdx.x;
    if (ei32[idx] != 0) atomicOr(&any, 1);
    __syncthreads();
    if (threadIdx.x == 0) g_is64 = (any == 0) ? 1 : 0;
}

// ---------------- edge scatter: agg[dst] += x[src] ----------------
__global__ void scatter_kernel(const float* __restrict__ x,
                               const void* __restrict__ eiv,
                               int E, float* __restrict__ agg) {
    int gw   = (blockIdx.x * blockDim.x + threadIdx.x) >> 5;
    int lane = threadIdx.x & 31;
    if (gw >= E) return;
    long long s, d;
    if (g_is64) {
        const long long* ei = (const long long*)eiv;
        s = ei[gw]; d = ei[E + gw];
    } else {
        const int* ei = (const int*)eiv;
        s = ei[gw]; d = ei[E + gw];
    }
    if ((unsigned long long)s >= N_NODES || (unsigned long long)d >= N_NODES) return;
    float4 v = *(const float4*)(x + (size_t)s * DK + lane * 4);
    float* p = agg + (size_t)d * DK + lane * 4;
    asm volatile("red.global.add.v4.f32 [%0], {%1, %2, %3, %4};"
                 :: "l"(p), "f"(v.x), "f"(v.y), "f"(v.z), "f"(v.w)
                 : "memory");
}

// ---------------- mma.sync tf32 GEMM ----------------
// out[r,:] = A[r,:128]@Wl + X[r,:128]@Wr + b    (fp32 accum)
// CTA: 128 rows x DOUT cols, 256 threads = 8 warps (4 row-groups x 2 col-groups).
// K processed in 32-wide chunks; 8 chunks total (4 from A/Wl, 4 from X/Wr),
// double-buffered in shared memory. tf32 conversion at STS time (cvt.rna).

template<int DOUT>
struct StageRegs {
    float4 rv[4];                       // 128x32 row chunk / 256 thr = 4 float4
    float4 wv[DOUT == 128 ? 4 : 2];     // 32xDOUT W chunk / 256 thr
};

template<int DOUT>
__device__ __forceinline__ void ldg_stage(StageRegs<DOUT>& R,
                                          const float* __restrict__ rows,
                                          const float* __restrict__ W,
                                          int k0, int row0, int nrows, int tid) {
#pragma unroll
    for (int j = 0; j < 4; j++) {
        int idx = tid + j * 256;
        int r = idx >> 3, c4 = idx & 7;
        float4 v = make_float4(0.f, 0.f, 0.f, 0.f);
        if (row0 + r < nrows)
            v = *(const float4*)&rows[(size_t)(row0 + r) * 128 + k0 + c4 * 4];
        R.rv[j] = v;
    }
    constexpr int WI = (DOUT == 128) ? 4 : 2;
#pragma unroll
    for (int j = 0; j < WI; j++) {
        int idx = tid + j * 256;
        int k, c4;
        if (DOUT == 128) { k = idx >> 5; c4 = idx & 31; }
        else             { k = idx >> 4; c4 = idx & 15; }
        R.wv[j] = *(const float4*)&W[(size_t)(k0 + k) * DOUT + c4 * 4];
    }
}

template<int DOUT>
__device__ __forceinline__ void sts_stage(const StageRegs<DOUT>& R,
                                          uint32_t* sA, uint32_t* sW, int tid) {
    constexpr int WST = DOUT + 8;
#pragma unroll
    for (int j = 0; j < 4; j++) {
        int idx = tid + j * 256;
        int r = idx >> 3, c4 = idx & 7;
        float4 v = R.rv[j];
        *(uint4*)&sA[r * 36 + c4 * 4] =
            make_uint4(f2tf(v.x), f2tf(v.y), f2tf(v.z), f2tf(v.w));
    }
    constexpr int WI = (DOUT == 128) ? 4 : 2;
#pragma unroll
    for (int j = 0; j < WI; j++) {
        int idx = tid + j * 256;
        int k, c4;
        if (DOUT == 128) { k = idx >> 5; c4 = idx & 31; }
        else             { k = idx >> 4; c4 = idx & 15; }
        float4 v = R.wv[j];
        *(uint4*)&sW[k * WST + c4 * 4] =
            make_uint4(f2tf(v.x), f2tf(v.y), f2tf(v.z), f2tf(v.w));
    }
}

template<int DOUT>
__global__ void __launch_bounds__(256, 1)
gemm_mma(const float* __restrict__ A, const float* __restrict__ X,
         const float* __restrict__ Wl, const float* __restrict__ Wr,
         const float* __restrict__ bias, float* __restrict__ out, int nrows) {
    constexpr int WST = DOUT + 8;          // W smem row stride (floats)
    constexpr int NT  = DOUT / 16;         // col tiles per warp (8-wide each)
    constexpr int ASZ = 128 * 36;
    constexpr int WSZ = 32 * WST;

    extern __shared__ uint32_t sm[];
    uint32_t* sA[2] = { sm, sm + ASZ };
    uint32_t* sW[2] = { sm + 2 * ASZ, sm + 2 * ASZ + WSZ };

    int tid  = threadIdx.x;
    int wid  = tid >> 5, lane = tid & 31;
    int wr   = wid & 3, wc = wid >> 2;     // warp row/col group
    int g    = lane >> 2, tg = lane & 3;   // mma fragment ids
    int row0 = blockIdx.x * 128;

    float acc[2][NT][4];
#pragma unroll
    for (int rt = 0; rt < 2; rt++)
#pragma unroll
        for (int ct = 0; ct < NT; ct++)
#pragma unroll
            for (int j = 0; j < 4; j++) acc[rt][ct][j] = 0.f;

    // stage s: s<4 -> (A, Wl), s>=4 -> (X, Wr); k0 = (s&3)*32
    StageRegs<DOUT> R;
    ldg_stage<DOUT>(R, A, Wl, 0, row0, nrows, tid);
    sts_stage<DOUT>(R, sA[0], sW[0], tid);

#pragma unroll
    for (int s = 0; s < 8; s++) {
        if (s + 1 < 8) {
            const float* rows = (s + 1 < 4) ? A : X;
            const float* W    = (s + 1 < 4) ? Wl : Wr;
            ldg_stage<DOUT>(R, rows, W, ((s + 1) & 3) * 32, row0, nrows, tid);
        }
        __syncthreads();                      // prior compute done; STS(s) visible
        if (s + 1 < 8) sts_stage<DOUT>(R, sA[(s + 1) & 1], sW[(s + 1) & 1], tid);

        const uint32_t* As = sA[s & 1];
        const uint32_t* Ws = sW[s & 1];
#pragma unroll
        for (int kk = 0; kk < 32; kk += 8) {
            uint32_t a[2][4];
#pragma unroll
            for (int rt = 0; rt < 2; rt++) {
                int rb = wr * 32 + rt * 16;
                a[rt][0] = As[(rb + g) * 36 + kk + tg];
                a[rt][1] = As[(rb + g + 8) * 36 + kk + tg];
                a[rt][2] = As[(rb + g) * 36 + kk + tg + 4];
                a[rt][3] = As[(rb + g + 8) * 36 + kk + tg + 4];
            }
#pragma unroll
            for (int ct = 0; ct < NT; ct++) {
                int nb = wc * (DOUT / 2) + ct * 8 + g;
                uint32_t b0 = Ws[(kk + tg) * WST + nb];
                uint32_t b1 = Ws[(kk + tg + 4) * WST + nb];
                mma_tf32(acc[0][ct], a[0], b0, b1);
                mma_tf32(acc[1][ct], a[1], b0, b1);
            }
        }
    }

    // epilogue: bias add + store (c0,c1 -> row g; c2,c3 -> row g+8)
#pragma unroll
    for (int rt = 0; rt < 2; rt++) {
        int gr = row0 + wr * 32 + rt * 16 + g;
#pragma unroll
        for (int ct = 0; ct < NT; ct++) {
            int nb = wc * (DOUT / 2) + ct * 8 + 2 * tg;
            float b0 = bias[nb], b1 = bias[nb + 1];
            if (gr < nrows)
                *(float2*)&out[(size_t)gr * DOUT + nb] =
                    make_float2(acc[rt][ct][0] + b0, acc[rt][ct][1] + b1);
            if (gr + 8 < nrows)
                *(float2*)&out[(size_t)(gr + 8) * DOUT + nb] =
                    make_float2(acc[rt][ct][2] + b0, acc[rt][ct][3] + b1);
        }
    }
}

// ---------------- column stats (sum, sumsq) over h[N,128] ----------------
__global__ void col_stats(const float* __restrict__ h, float* __restrict__ stats, int n) {
    __shared__ float red[512];
    int tid = threadIdx.x;
    int col = tid & 127, rh = tid >> 7;
    float s = 0.f, q = 0.f;
    for (int r = blockIdx.x * 2 + rh; r < n; r += gridDim.x * 2) {
        float v = h[(size_t)r * 128 + col];
        s += v; q += v * v;
    }
    red[tid] = s; red[256 + tid] = q;
    __syncthreads();
    if (tid < 128) {
        s = red[tid] + red[tid + 128];
        q = red[256 + tid] + red[256 + tid + 128];
        atomicAdd(&stats[tid], s);
        atomicAdd(&stats[DK + tid], q);
    }
}

// ---------------- BN finalize ----------------
__global__ void finalize_kernel(const float* __restrict__ stats,
                                const float* __restrict__ g,
                                const float* __restrict__ be,
                                float* __restrict__ ss, float invn) {
    int c = threadIdx.x;
    if (c < DK) {
        float mu  = stats[c] * invn;
        float var = stats[DK + c] * invn - mu * mu;
        float rs  = rsqrtf(var + BN_EPS);
        float s   = g[c] * rs;
        ss[c]      = s;
        ss[DK + c] = be[c] - mu * s;
    }
}

// ---------------- BN apply + exact GELU ----------------
__device__ __forceinline__ float gelu_exact(float v) {
    return 0.5f * v * (1.0f + erff(v * 0.70710678118654752f));
}

__global__ void bn_gelu_kernel(const float* __restrict__ h,
                               const float* __restrict__ ss,
                               float* __restrict__ out, int n4) {
    int i = blockIdx.x * blockDim.x + threadIdx.x;
    if (i >= n4) return;
    int c4 = i & (DK / 4 - 1);
    float4 v  = ((const float4*)h)[i];
    float4 sc = ((const float4*)ss)[c4];
    float4 sh = ((const float4*)(ss + DK))[c4];
    v.x = gelu_exact(v.x * sc.x + sh.x);
    v.y = gelu_exact(v.y * sc.y + sh.y);
    v.z = gelu_exact(v.z * sc.z + sh.z);
    v.w = gelu_exact(v.w * sc.w + sh.w);
    ((float4*)out)[i] = v;
}

// ---------------- launch ----------------
extern "C" void kernel_launch(void* const* d_in, const int* in_sizes, int n_in,
                              void* d_out, int out_size) {
    const float* x   = (const float*)d_in[0];
    const void*  ei  = d_in[1];
    const float* W0l = (const float*)d_in[2];
    const float* W0r = (const float*)d_in[3];
    const float* b0  = (const float*)d_in[4];
    const float* g0  = (const float*)d_in[5];
    const float* be0 = (const float*)d_in[6];
    const float* W1l = (const float*)d_in[7];
    const float* W1r = (const float*)d_in[8];
    const float* b1  = (const float*)d_in[9];
    const float* g1  = (const float*)d_in[10];
    const float* be1 = (const float*)d_in[11];
    const float* W2l = (const float*)d_in[12];
    const float* W2r = (const float*)d_in[13];
    const float* b2  = (const float*)d_in[14];
    float* out = (float*)d_out;

    int E = in_sizes[1] / 2;

    void* p;
    cudaGetSymbolAddress(&p, g_agg);   float* agg   = (float*)p;
    cudaGetSymbolAddress(&p, g_h);     float* h     = (float*)p;
    cudaGetSymbolAddress(&p, g_x1);    float* x1    = (float*)p;
    cudaGetSymbolAddress(&p, g_stats); float* stats = (float*)p;
    cudaGetSymbolAddress(&p, g_ss);    float* ss    = (float*)p;

    const int smemA = 2 * (128 * 36 + 32 * (DK + 8)) * 4;     // 71680
    const int smemB = 2 * (128 * 36 + 32 * (DOUT2 + 8)) * 4;  // 55296
    cudaFuncSetAttribute(gemm_mma<DK>,    cudaFuncAttributeMaxDynamicSharedMemorySize, smemA);
    cudaFuncSetAttribute(gemm_mma<DOUT2>, cudaFuncAttributeMaxDynamicSharedMemorySize, smemB);

    int zb      = (N_NODES * DK / 4 + 255) / 256;
    int sbl     = (E * 32 + 255) / 256;
    int gblocks = (N_NODES + 127) / 128;
    int n4      = N_NODES * DK / 4;
    int bgb     = (n4 + 255) / 256;
    float invn  = 1.0f / (float)N_NODES;

    detect_kernel<<<1, 128>>>((const int*)ei);

    // ---- layer 0 ----
    zero_kernel<<<zb, 256>>>((float4*)agg, N_NODES * DK / 4);
    zero_kernel<<<1, 64>>>((float4*)stats, 2 * DK / 4);
    scatter_kernel<<<sbl, 256>>>(x, ei, E, agg);
    gemm_mma<DK><<<gblocks, 256, smemA>>>(agg, x, W0l, W0r, b0, h, N_NODES);
    col_stats<<<256, 256>>>(h, stats, N_NODES);
    finalize_kernel<<<1, 128>>>(stats, g0, be0, ss, invn);
    bn_gelu_kernel<<<bgb, 256>>>(h, ss, x1, n4);

    // ---- layer 1 ----
    zero_kernel<<<zb, 256>>>((float4*)agg, N_NODES * DK / 4);
    zero_kernel<<<1, 64>>>((float4*)stats, 2 * DK / 4);
    scatter_kernel<<<sbl, 256>>>(x1, ei, E, agg);
    gemm_mma<DK><<<gblocks, 256, smemA>>>(agg, x1, W1l, W1r, b1, h, N_NODES);
    col_stats<<<256, 256>>>(h, stats, N_NODES);
    finalize_kernel<<<1, 128>>>(stats, g1, be1, ss, invn);
    bn_gelu_kernel<<<bgb, 256>>>(h, ss, x1, n4);

    // ---- layer 2 (no BN/GELU) ----
    zero_kernel<<<zb, 256>>>((float4*)agg, N_NODES * DK / 4);
    scatter_kernel<<<sbl, 256>>>(x1, ei, E, agg);
    gemm_mma<DOUT2><<<gblocks, 256, smemB>>>(agg, x1, W2l, W2r, b2, out, N_NODES);
}

// round 4
// speedup vs baseline: 2.2848x; 1.3645x over previous
#include <cuda_runtime.h>
#include <math.h>
#include <stdint.h>

#define N_NODES 50000
#define E_MAX   1000000
#define DK 128
#define DOUT2 64
#define BN_EPS 1e-5f

// ---------------- scratch ----------------
__device__ float g_agg[N_NODES * DK];
__device__ float g_h[N_NODES * DK];
__device__ float g_x1[N_NODES * DK];
__device__ float g_stats[2 * DK];
__device__ float g_ss[2 * DK];
__device__ int   g_is64;
__device__ int   g_deg[N_NODES];
__device__ int   g_rowptr[N_NODES + 1];
__device__ int   g_cur[N_NODES];
__device__ int   g_eidx[E_MAX];

// ---------------- helpers ----------------
__device__ __forceinline__ uint32_t f2tf(float f) {
    uint32_t r; asm("cvt.rna.tf32.f32 %0, %1;" : "=r"(r) : "f"(f)); return r;
}
__device__ __forceinline__ void mma_tf32(float* c, const uint32_t* a,
                                         uint32_t b0, uint32_t b1) {
    asm volatile(
        "mma.sync.aligned.m16n8k8.row.col.f32.tf32.tf32.f32 "
        "{%0,%1,%2,%3}, {%4,%5,%6,%7}, {%8,%9}, {%0,%1,%2,%3};"
        : "+f"(c[0]), "+f"(c[1]), "+f"(c[2]), "+f"(c[3])
        : "r"(a[0]), "r"(a[1]), "r"(a[2]), "r"(a[3]), "r"(b0), "r"(b1));
}

// ---------------- utility kernels ----------------
__global__ void zero_kernel(float4* p, int n4) {
    int i = blockIdx.x * blockDim.x + threadIdx.x;
    if (i < n4) p[i] = make_float4(0.f, 0.f, 0.f, 0.f);
}
__global__ void zero_int_kernel(int* p, int n) {
    int i = blockIdx.x * blockDim.x + threadIdx.x;
    if (i < n) p[i] = 0;
}

__global__ void detect_kernel(const int* __restrict__ ei32) {
    __shared__ int any;
    if (threadIdx.x == 0) any = 0;
    __syncthreads();
    int idx = 1 + 2 * threadIdx.x;
    if (ei32[idx] != 0) atomicOr(&any, 1);
    __syncthreads();
    if (threadIdx.x == 0) g_is64 = (any == 0) ? 1 : 0;
}

// ---------------- CSR build ----------------
__global__ void hist_kernel(const void* __restrict__ eiv, int E) {
    int i = blockIdx.x * blockDim.x + threadIdx.x;
    if (i >= E) return;
    long long d;
    if (g_is64) d = ((const long long*)eiv)[E + i];
    else        d = ((const int*)eiv)[E + i];
    if ((unsigned long long)d < N_NODES) atomicAdd(&g_deg[(int)d], 1);
}

// one-block exclusive scan of g_deg -> g_rowptr, g_cur
__global__ void scan_kernel(int E) {
    constexpr int CH = (N_NODES + 1023) / 1024;   // 49
    __shared__ int sm[1024];
    int t = threadIdx.x;
    int base = t * CH;
    int sum = 0;
    for (int i = 0; i < CH; i++) {
        int idx = base + i;
        if (idx < N_NODES) sum += g_deg[idx];
    }
    sm[t] = sum;
    __syncthreads();
    // inclusive Hillis-Steele
    for (int off = 1; off < 1024; off <<= 1) {
        int v = (t >= off) ? sm[t - off] : 0;
        __syncthreads();
        sm[t] += v;
        __syncthreads();
    }
    int excl = (t == 0) ? 0 : sm[t - 1];
    int off = excl;
    for (int i = 0; i < CH; i++) {
        int idx = base + i;
        if (idx < N_NODES) {
            g_rowptr[idx] = off;
            g_cur[idx]    = off;
            off += g_deg[idx];
        }
    }
    if (t == 1023) g_rowptr[N_NODES] = sm[1023];
}

__global__ void fill_kernel(const void* __restrict__ eiv, int E) {
    int i = blockIdx.x * blockDim.x + threadIdx.x;
    if (i >= E) return;
    long long s, d;
    if (g_is64) {
        s = ((const long long*)eiv)[i];
        d = ((const long long*)eiv)[E + i];
    } else {
        s = ((const int*)eiv)[i];
        d = ((const int*)eiv)[E + i];
    }
    if ((unsigned long long)s >= N_NODES || (unsigned long long)d >= N_NODES) return;
    int pos = atomicAdd(&g_cur[(int)d], 1);
    g_eidx[pos] = (int)s;
}

// ---------------- gather: agg[n] = sum_{e in CSR[n]} x[eidx[e]] ----------------
__global__ void __launch_bounds__(256)
gather_kernel(const float* __restrict__ x, float* __restrict__ agg) {
    int node = (blockIdx.x * blockDim.x + threadIdx.x) >> 5;
    int lane = threadIdx.x & 31;
    if (node >= N_NODES) return;
    int beg = g_rowptr[node];
    int end = g_rowptr[node + 1];

    float4 a0 = make_float4(0.f, 0.f, 0.f, 0.f);
    float4 a1 = make_float4(0.f, 0.f, 0.f, 0.f);

    for (int base = beg; base < end; base += 32) {
        int n = end - base; if (n > 32) n = 32;
        int myidx = (base + lane < end) ? g_eidx[base + lane] : 0;
        int j = 0;
        for (; j + 1 < n; j += 2) {
            int s0 = __shfl_sync(0xffffffffu, myidx, j);
            int s1 = __shfl_sync(0xffffffffu, myidx, j + 1);
            float4 v0 = *(const float4*)(x + (size_t)s0 * DK + lane * 4);
            float4 v1 = *(const float4*)(x + (size_t)s1 * DK + lane * 4);
            a0.x += v0.x; a0.y += v0.y; a0.z += v0.z; a0.w += v0.w;
            a1.x += v1.x; a1.y += v1.y; a1.z += v1.z; a1.w += v1.w;
        }
        if (j < n) {
            int s0 = __shfl_sync(0xffffffffu, myidx, j);
            float4 v0 = *(const float4*)(x + (size_t)s0 * DK + lane * 4);
            a0.x += v0.x; a0.y += v0.y; a0.z += v0.z; a0.w += v0.w;
        }
    }
    a0.x += a1.x; a0.y += a1.y; a0.z += a1.z; a0.w += a1.w;
    *(float4*)(agg + (size_t)node * DK + lane * 4) = a0;
}

// ---------------- mma.sync tf32 GEMM ----------------
template<int DOUT>
struct StageRegs {
    float4 rv[4];
    float4 wv[DOUT == 128 ? 4 : 2];
};

template<int DOUT>
__device__ __forceinline__ void ldg_stage(StageRegs<DOUT>& R,
                                          const float* __restrict__ rows,
                                          const float* __restrict__ W,
                                          int k0, int row0, int nrows, int tid) {
#pragma unroll
    for (int j = 0; j < 4; j++) {
        int idx = tid + j * 256;
        int r = idx >> 3, c4 = idx & 7;
        float4 v = make_float4(0.f, 0.f, 0.f, 0.f);
        if (row0 + r < nrows)
            v = *(const float4*)&rows[(size_t)(row0 + r) * 128 + k0 + c4 * 4];
        R.rv[j] = v;
    }
    constexpr int WI = (DOUT == 128) ? 4 : 2;
#pragma unroll
    for (int j = 0; j < WI; j++) {
        int idx = tid + j * 256;
        int k, c4;
        if (DOUT == 128) { k = idx >> 5; c4 = idx & 31; }
        else             { k = idx >> 4; c4 = idx & 15; }
        R.wv[j] = *(const float4*)&W[(size_t)(k0 + k) * DOUT + c4 * 4];
    }
}

template<int DOUT>
__device__ __forceinline__ void sts_stage(const StageRegs<DOUT>& R,
                                          uint32_t* sA, uint32_t* sW, int tid) {
    constexpr int WST = DOUT + 8;
#pragma unroll
    for (int j = 0; j < 4; j++) {
        int idx = tid + j * 256;
        int r = idx >> 3, c4 = idx & 7;
        float4 v = R.rv[j];
        *(uint4*)&sA[r * 36 + c4 * 4] =
            make_uint4(f2tf(v.x), f2tf(v.y), f2tf(v.z), f2tf(v.w));
    }
    constexpr int WI = (DOUT == 128) ? 4 : 2;
#pragma unroll
    for (int j = 0; j < WI; j++) {
        int idx = tid + j * 256;
        int k, c4;
        if (DOUT == 128) { k = idx >> 5; c4 = idx & 31; }
        else             { k = idx >> 4; c4 = idx & 15; }
        float4 v = R.wv[j];
        *(uint4*)&sW[k * WST + c4 * 4] =
            make_uint4(f2tf(v.x), f2tf(v.y), f2tf(v.z), f2tf(v.w));
    }
}

template<int DOUT>
__global__ void __launch_bounds__(256, 1)
gemm_mma(const float* __restrict__ A, const float* __restrict__ X,
         const float* __restrict__ Wl, const float* __restrict__ Wr,
         const float* __restrict__ bias, float* __restrict__ out, int nrows) {
    constexpr int WST = DOUT + 8;
    constexpr int NT  = DOUT / 16;
    constexpr int ASZ = 128 * 36;
    constexpr int WSZ = 32 * WST;

    extern __shared__ uint32_t sm[];
    uint32_t* sA[2] = { sm, sm + ASZ };
    uint32_t* sW[2] = { sm + 2 * ASZ, sm + 2 * ASZ + WSZ };

    int tid  = threadIdx.x;
    int wid  = tid >> 5, lane = tid & 31;
    int wr   = wid & 3, wc = wid >> 2;
    int g    = lane >> 2, tg = lane & 3;
    int row0 = blockIdx.x * 128;

    float acc[2][NT][4];
#pragma unroll
    for (int rt = 0; rt < 2; rt++)
#pragma unroll
        for (int ct = 0; ct < NT; ct++)
#pragma unroll
            for (int j = 0; j < 4; j++) acc[rt][ct][j] = 0.f;

    StageRegs<DOUT> R;
    ldg_stage<DOUT>(R, A, Wl, 0, row0, nrows, tid);
    sts_stage<DOUT>(R, sA[0], sW[0], tid);

#pragma unroll
    for (int s = 0; s < 8; s++) {
        if (s + 1 < 8) {
            const float* rows = (s + 1 < 4) ? A : X;
            const float* W    = (s + 1 < 4) ? Wl : Wr;
            ldg_stage<DOUT>(R, rows, W, ((s + 1) & 3) * 32, row0, nrows, tid);
        }
        __syncthreads();
        if (s + 1 < 8) sts_stage<DOUT>(R, sA[(s + 1) & 1], sW[(s + 1) & 1], tid);

        const uint32_t* As = sA[s & 1];
        const uint32_t* Ws = sW[s & 1];
#pragma unroll
        for (int kk = 0; kk < 32; kk += 8) {
            uint32_t a[2][4];
#pragma unroll
            for (int rt = 0; rt < 2; rt++) {
                int rb = wr * 32 + rt * 16;
                a[rt][0] = As[(rb + g) * 36 + kk + tg];
                a[rt][1] = As[(rb + g + 8) * 36 + kk + tg];
                a[rt][2] = As[(rb + g) * 36 + kk + tg + 4];
                a[rt][3] = As[(rb + g + 8) * 36 + kk + tg + 4];
            }
#pragma unroll
            for (int ct = 0; ct < NT; ct++) {
                int nb = wc * (DOUT / 2) + ct * 8 + g;
                uint32_t b0 = Ws[(kk + tg) * WST + nb];
                uint32_t b1 = Ws[(kk + tg + 4) * WST + nb];
                mma_tf32(acc[0][ct], a[0], b0, b1);
                mma_tf32(acc[1][ct], a[1], b0, b1);
            }
        }
    }

#pragma unroll
    for (int rt = 0; rt < 2; rt++) {
        int gr = row0 + wr * 32 + rt * 16 + g;
#pragma unroll
        for (int ct = 0; ct < NT; ct++) {
            int nb = wc * (DOUT / 2) + ct * 8 + 2 * tg;
            float b0 = bias[nb], b1 = bias[nb + 1];
            if (gr < nrows)
                *(float2*)&out[(size_t)gr * DOUT + nb] =
                    make_float2(acc[rt][ct][0] + b0, acc[rt][ct][1] + b1);
            if (gr + 8 < nrows)
                *(float2*)&out[(size_t)(gr + 8) * DOUT + nb] =
                    make_float2(acc[rt][ct][2] + b0, acc[rt][ct][3] + b1);
        }
    }
}

// ---------------- column stats ----------------
__global__ void col_stats(const float* __restrict__ h, float* __restrict__ stats, int n) {
    __shared__ float red[512];
    int tid = threadIdx.x;
    int col = tid & 127, rh = tid >> 7;
    float s = 0.f, q = 0.f;
    for (int r = blockIdx.x * 2 + rh; r < n; r += gridDim.x * 2) {
        float v = h[(size_t)r * 128 + col];
        s += v; q += v * v;
    }
    red[tid] = s; red[256 + tid] = q;
    __syncthreads();
    if (tid < 128) {
        s = red[tid] + red[tid + 128];
        q = red[256 + tid] + red[256 + tid + 128];
        atomicAdd(&stats[tid], s);
        atomicAdd(&stats[DK + tid], q);
    }
}

// ---------------- BN finalize ----------------
__global__ void finalize_kernel(const float* __restrict__ stats,
                                const float* __restrict__ g,
                                const float* __restrict__ be,
                                float* __restrict__ ss, float invn) {
    int c = threadIdx.x;
    if (c < DK) {
        float mu  = stats[c] * invn;
        float var = stats[DK + c] * invn - mu * mu;
        float rs  = rsqrtf(var + BN_EPS);
        float s   = g[c] * rs;
        ss[c]      = s;
        ss[DK + c] = be[c] - mu * s;
    }
}

// ---------------- BN apply + exact GELU ----------------
__device__ __forceinline__ float gelu_exact(float v) {
    return 0.5f * v * (1.0f + erff(v * 0.70710678118654752f));
}

__global__ void bn_gelu_kernel(const float* __restrict__ h,
                               const float* __restrict__ ss,
                               float* __restrict__ out, int n4) {
    int i = blockIdx.x * blockDim.x + threadIdx.x;
    if (i >= n4) return;
    int c4 = i & (DK / 4 - 1);
    float4 v  = ((const float4*)h)[i];
    float4 sc = ((const float4*)ss)[c4];
    float4 sh = ((const float4*)(ss + DK))[c4];
    v.x = gelu_exact(v.x * sc.x + sh.x);
    v.y = gelu_exact(v.y * sc.y + sh.y);
    v.z = gelu_exact(v.z * sc.z + sh.z);
    v.w = gelu_exact(v.w * sc.w + sh.w);
    ((float4*)out)[i] = v;
}

// ---------------- launch ----------------
extern "C" void kernel_launch(void* const* d_in, const int* in_sizes, int n_in,
                              void* d_out, int out_size) {
    const float* x   = (const float*)d_in[0];
    const void*  ei  = d_in[1];
    const float* W0l = (const float*)d_in[2];
    const float* W0r = (const float*)d_in[3];
    const float* b0  = (const float*)d_in[4];
    const float* g0  = (const float*)d_in[5];
    const float* be0 = (const float*)d_in[6];
    const float* W1l = (const float*)d_in[7];
    const float* W1r = (const float*)d_in[8];
    const float* b1  = (const float*)d_in[9];
    const float* g1  = (const float*)d_in[10];
    const float* be1 = (const float*)d_in[11];
    const float* W2l = (const float*)d_in[12];
    const float* W2r = (const float*)d_in[13];
    const float* b2  = (const float*)d_in[14];
    float* out = (float*)d_out;

    int E = in_sizes[1] / 2;
    if (E > E_MAX) E = E_MAX;

    void* p;
    cudaGetSymbolAddress(&p, g_agg);   float* agg   = (float*)p;
    cudaGetSymbolAddress(&p, g_h);     float* h     = (float*)p;
    cudaGetSymbolAddress(&p, g_x1);    float* x1    = (float*)p;
    cudaGetSymbolAddress(&p, g_stats); float* stats = (float*)p;
    cudaGetSymbolAddress(&p, g_ss);    float* ss    = (float*)p;
    cudaGetSymbolAddress(&p, g_deg);   int*   deg   = (int*)p;

    const int smemA = 2 * (128 * 36 + 32 * (DK + 8)) * 4;
    const int smemB = 2 * (128 * 36 + 32 * (DOUT2 + 8)) * 4;
    cudaFuncSetAttribute(gemm_mma<DK>,    cudaFuncAttributeMaxDynamicSharedMemorySize, smemA);
    cudaFuncSetAttribute(gemm_mma<DOUT2>, cudaFuncAttributeMaxDynamicSharedMemorySize, smemB);

    int eb      = (E + 255) / 256;
    int gblocks = (N_NODES + 127) / 128;
    int gab     = (N_NODES * 32 + 255) / 256;
    int n4      = N_NODES * DK / 4;
    int bgb     = (n4 + 255) / 256;
    float invn  = 1.0f / (float)N_NODES;

    // ---- CSR build (once; reused by all 3 layers) ----
    detect_kernel<<<1, 128>>>((const int*)ei);
    zero_int_kernel<<<(N_NODES + 255) / 256, 256>>>(deg, N_NODES);
    hist_kernel<<<eb, 256>>>(ei, E);
    scan_kernel<<<1, 1024>>>(E);
    fill_kernel<<<eb, 256>>>(ei, E);

    // ---- layer 0 ----
    zero_kernel<<<1, 64>>>((float4*)stats, 2 * DK / 4);
    gather_kernel<<<gab, 256>>>(x, agg);
    gemm_mma<DK><<<gblocks, 256, smemA>>>(agg, x, W0l, W0r, b0, h, N_NODES);
    col_stats<<<256, 256>>>(h, stats, N_NODES);
    finalize_kernel<<<1, 128>>>(stats, g0, be0, ss, invn);
    bn_gelu_kernel<<<bgb, 256>>>(h, ss, x1, n4);

    // ---- layer 1 ----
    zero_kernel<<<1, 64>>>((float4*)stats, 2 * DK / 4);
    gather_kernel<<<gab, 256>>>(x1, agg);
    gemm_mma<DK><<<gblocks, 256, smemA>>>(agg, x1, W1l, W1r, b1, h, N_NODES);
    col_stats<<<256, 256>>>(h, stats, N_NODES);
    finalize_kernel<<<1, 128>>>(stats, g1, be1, ss, invn);
    bn_gelu_kernel<<<bgb, 256>>>(h, ss, x1, n4);

    // ---- layer 2 (no BN/GELU) ----
    gather_kernel<<<gab, 256>>>(x1, agg);
    gemm_mma<DOUT2><<<gblocks, 256, smemB>>>(agg, x1, W2l, W2r, b2, out, N_NODES);
}

// round 5
// speedup vs baseline: 2.8987x; 1.2687x over previous
#include <cuda_runtime.h>
#include <math.h>
#include <stdint.h>

#define N_NODES 50000
#define E_MAX   1000000
#define DK 128
#define DOUT2 64
#define BN_EPS 1e-5f
#define SCAN_B 1024
#define SCAN_G ((N_NODES + SCAN_B - 1) / SCAN_B)   // 49

// ---------------- scratch ----------------
__device__ float g_agg[N_NODES * DK];
__device__ float g_h[N_NODES * DK];
__device__ float g_x1[N_NODES * DK];
__device__ float g_stats[2 * DK];
__device__ float g_ss[2 * DK];
__device__ int   g_is64;
__device__ int   g_deg[N_NODES];
__device__ int   g_rowptr[N_NODES + 1];
__device__ int   g_cur[N_NODES];
__device__ int   g_eidx[E_MAX];
__device__ int   g_part[SCAN_G];
__device__ int   g_partoff[SCAN_G + 1];

// ---------------- helpers ----------------
__device__ __forceinline__ uint32_t f2tf(float f) {
    uint32_t r; asm("cvt.rna.tf32.f32 %0, %1;" : "=r"(r) : "f"(f)); return r;
}
__device__ __forceinline__ void mma_tf32(float* c, const uint32_t* a,
                                         uint32_t b0, uint32_t b1) {
    asm volatile(
        "mma.sync.aligned.m16n8k8.row.col.f32.tf32.tf32.f32 "
        "{%0,%1,%2,%3}, {%4,%5,%6,%7}, {%8,%9}, {%0,%1,%2,%3};"
        : "+f"(c[0]), "+f"(c[1]), "+f"(c[2]), "+f"(c[3])
        : "r"(a[0]), "r"(a[1]), "r"(a[2]), "r"(a[3]), "r"(b0), "r"(b1));
}

// ---------------- utility kernels ----------------
__global__ void zero_kernel(float4* p, int n4) {
    int i = blockIdx.x * blockDim.x + threadIdx.x;
    if (i < n4) p[i] = make_float4(0.f, 0.f, 0.f, 0.f);
}
__global__ void zero_int_kernel(int* p, int n) {
    int i = blockIdx.x * blockDim.x + threadIdx.x;
    if (i < n) p[i] = 0;
}

__global__ void detect_kernel(const int* __restrict__ ei32) {
    __shared__ int any;
    if (threadIdx.x == 0) any = 0;
    __syncthreads();
    int idx = 1 + 2 * threadIdx.x;
    if (ei32[idx] != 0) atomicOr(&any, 1);
    __syncthreads();
    if (threadIdx.x == 0) g_is64 = (any == 0) ? 1 : 0;
}

// ---------------- CSR build ----------------
__global__ void hist_kernel(const void* __restrict__ eiv, int E) {
    int i = blockIdx.x * blockDim.x + threadIdx.x;
    if (i >= E) return;
    long long d;
    if (g_is64) d = ((const long long*)eiv)[E + i];
    else        d = ((const int*)eiv)[E + i];
    if ((unsigned long long)d < N_NODES) atomicAdd(&g_deg[(int)d], 1);
}

// phase 1: per-block sums of g_deg
__global__ void block_reduce_kernel() {
    __shared__ int sm[32];
    int idx = blockIdx.x * SCAN_B + threadIdx.x;
    int v = (idx < N_NODES) ? g_deg[idx] : 0;
#pragma unroll
    for (int o = 16; o > 0; o >>= 1) v += __shfl_down_sync(0xffffffffu, v, o);
    if ((threadIdx.x & 31) == 0) sm[threadIdx.x >> 5] = v;
    __syncthreads();
    if (threadIdx.x < 32) {
        int w = sm[threadIdx.x];
#pragma unroll
        for (int o = 16; o > 0; o >>= 1) w += __shfl_down_sync(0xffffffffu, w, o);
        if (threadIdx.x == 0) g_part[blockIdx.x] = w;
    }
}

// phase 2: exclusive scan of SCAN_G partials (1 small block)
__global__ void scan_partials_kernel() {
    __shared__ int sm[SCAN_G + 1];
    int t = threadIdx.x;
    if (t == 0) {
        int acc = 0;
        for (int i = 0; i < SCAN_G; i++) { sm[i] = acc; acc += g_part[i]; }
        sm[SCAN_G] = acc;
    }
    __syncthreads();
    if (t <= SCAN_G) g_partoff[t] = sm[t];
}

// phase 3: per-block exclusive scan + offset -> rowptr, cur
__global__ void block_scan_kernel() {
    __shared__ int warp_sums[32];
    int idx = blockIdx.x * SCAN_B + threadIdx.x;
    int lane = threadIdx.x & 31, warp = threadIdx.x >> 5;
    int v = (idx < N_NODES) ? g_deg[idx] : 0;
    // inclusive warp scan
    int s = v;
#pragma unroll
    for (int o = 1; o < 32; o <<= 1) {
        int u = __shfl_up_sync(0xffffffffu, s, o);
        if (lane >= o) s += u;
    }
    if (lane == 31) warp_sums[warp] = s;
    __syncthreads();
    if (warp == 0) {
        int w = (lane < 32) ? warp_sums[lane] : 0;
        int ws = w;
#pragma unroll
        for (int o = 1; o < 32; o <<= 1) {
            int u = __shfl_up_sync(0xffffffffu, ws, o);
            if (lane >= o) ws += u;
        }
        warp_sums[lane] = ws - w;   // exclusive
    }
    __syncthreads();
    int excl = s - v + warp_sums[warp] + g_partoff[blockIdx.x];
    if (idx < N_NODES) {
        g_rowptr[idx] = excl;
        g_cur[idx]    = excl;
        if (idx == N_NODES - 1) g_rowptr[N_NODES] = excl + v;
    }
}

__global__ void fill_kernel(const void* __restrict__ eiv, int E) {
    int i = blockIdx.x * blockDim.x + threadIdx.x;
    if (i >= E) return;
    long long s, d;
    if (g_is64) {
        s = ((const long long*)eiv)[i];
        d = ((const long long*)eiv)[E + i];
    } else {
        s = ((const int*)eiv)[i];
        d = ((const int*)eiv)[E + i];
    }
    if ((unsigned long long)s >= N_NODES || (unsigned long long)d >= N_NODES) return;
    int pos = atomicAdd(&g_cur[(int)d], 1);
    g_eidx[pos] = (int)s;
}

// ---------------- gather: agg[n] = sum_{e in CSR[n]} x[eidx[e]] ----------------
__global__ void __launch_bounds__(256)
gather_kernel(const float* __restrict__ x, float* __restrict__ agg) {
    int node = (blockIdx.x * blockDim.x + threadIdx.x) >> 5;
    int lane = threadIdx.x & 31;
    if (node >= N_NODES) return;
    int beg = g_rowptr[node];
    int end = g_rowptr[node + 1];

    float4 a0 = make_float4(0.f, 0.f, 0.f, 0.f);
    float4 a1 = make_float4(0.f, 0.f, 0.f, 0.f);

    for (int base = beg; base < end; base += 32) {
        int n = end - base; if (n > 32) n = 32;
        int myidx = (base + lane < end) ? g_eidx[base + lane] : 0;
        int j = 0;
        for (; j + 1 < n; j += 2) {
            int s0 = __shfl_sync(0xffffffffu, myidx, j);
            int s1 = __shfl_sync(0xffffffffu, myidx, j + 1);
            float4 v0 = *(const float4*)(x + (size_t)s0 * DK + lane * 4);
            float4 v1 = *(const float4*)(x + (size_t)s1 * DK + lane * 4);
            a0.x += v0.x; a0.y += v0.y; a0.z += v0.z; a0.w += v0.w;
            a1.x += v1.x; a1.y += v1.y; a1.z += v1.z; a1.w += v1.w;
        }
        if (j < n) {
            int s0 = __shfl_sync(0xffffffffu, myidx, j);
            float4 v0 = *(const float4*)(x + (size_t)s0 * DK + lane * 4);
            a0.x += v0.x; a0.y += v0.y; a0.z += v0.z; a0.w += v0.w;
        }
    }
    a0.x += a1.x; a0.y += a1.y; a0.z += a1.z; a0.w += a1.w;
    *(float4*)(agg + (size_t)node * DK + lane * 4) = a0;
}

// ---------------- mma.sync tf32 GEMM ----------------
template<int DOUT>
struct StageRegs {
    float4 rv[4];
    float4 wv[DOUT == 128 ? 4 : 2];
};

template<int DOUT>
__device__ __forceinline__ void ldg_stage(StageRegs<DOUT>& R,
                                          const float* __restrict__ rows,
                                          const float* __restrict__ W,
                                          int k0, int row0, int nrows, int tid) {
#pragma unroll
    for (int j = 0; j < 4; j++) {
        int idx = tid + j * 256;
        int r = idx >> 3, c4 = idx & 7;
        float4 v = make_float4(0.f, 0.f, 0.f, 0.f);
        if (row0 + r < nrows)
            v = *(const float4*)&rows[(size_t)(row0 + r) * 128 + k0 + c4 * 4];
        R.rv[j] = v;
    }
    constexpr int WI = (DOUT == 128) ? 4 : 2;
#pragma unroll
    for (int j = 0; j < WI; j++) {
        int idx = tid + j * 256;
        int k, c4;
        if (DOUT == 128) { k = idx >> 5; c4 = idx & 31; }
        else             { k = idx >> 4; c4 = idx & 15; }
        R.wv[j] = *(const float4*)&W[(size_t)(k0 + k) * DOUT + c4 * 4];
    }
}

template<int DOUT>
__device__ __forceinline__ void sts_stage(const StageRegs<DOUT>& R,
                                          uint32_t* sA, uint32_t* sW, int tid) {
    constexpr int WST = DOUT + 8;
#pragma unroll
    for (int j = 0; j < 4; j++) {
        int idx = tid + j * 256;
        int r = idx >> 3, c4 = idx & 7;
        float4 v = R.rv[j];
        *(uint4*)&sA[r * 36 + c4 * 4] =
            make_uint4(f2tf(v.x), f2tf(v.y), f2tf(v.z), f2tf(v.w));
    }
    constexpr int WI = (DOUT == 128) ? 4 : 2;
#pragma unroll
    for (int j = 0; j < WI; j++) {
        int idx = tid + j * 256;
        int k, c4;
        if (DOUT == 128) { k = idx >> 5; c4 = idx & 31; }
        else             { k = idx >> 4; c4 = idx & 15; }
        float4 v = R.wv[j];
        *(uint4*)&sW[k * WST + c4 * 4] =
            make_uint4(f2tf(v.x), f2tf(v.y), f2tf(v.z), f2tf(v.w));
    }
}

template<int DOUT>
__global__ void __launch_bounds__(256, 1)
gemm_mma(const float* __restrict__ A, const float* __restrict__ X,
         const float* __restrict__ Wl, const float* __restrict__ Wr,
         const float* __restrict__ bias, float* __restrict__ out, int nrows) {
    constexpr int WST = DOUT + 8;
    constexpr int NT  = DOUT / 16;
    constexpr int ASZ = 128 * 36;
    constexpr int WSZ = 32 * WST;

    extern __shared__ uint32_t sm[];
    uint32_t* sA[2] = { sm, sm + ASZ };
    uint32_t* sW[2] = { sm + 2 * ASZ, sm + 2 * ASZ + WSZ };

    int tid  = threadIdx.x;
    int wid  = tid >> 5, lane = tid & 31;
    int wr   = wid & 3, wc = wid >> 2;
    int g    = lane >> 2, tg = lane & 3;
    int row0 = blockIdx.x * 128;

    float acc[2][NT][4];
#pragma unroll
    for (int rt = 0; rt < 2; rt++)
#pragma unroll
        for (int ct = 0; ct < NT; ct++)
#pragma unroll
            for (int j = 0; j < 4; j++) acc[rt][ct][j] = 0.f;

    StageRegs<DOUT> R;
    ldg_stage<DOUT>(R, A, Wl, 0, row0, nrows, tid);
    sts_stage<DOUT>(R, sA[0], sW[0], tid);

#pragma unroll
    for (int s = 0; s < 8; s++) {
        if (s + 1 < 8) {
            const float* rows = (s + 1 < 4) ? A : X;
            const float* W    = (s + 1 < 4) ? Wl : Wr;
            ldg_stage<DOUT>(R, rows, W, ((s + 1) & 3) * 32, row0, nrows, tid);
        }
        __syncthreads();
        if (s + 1 < 8) sts_stage<DOUT>(R, sA[(s + 1) & 1], sW[(s + 1) & 1], tid);

        const uint32_t* As = sA[s & 1];
        const uint32_t* Ws = sW[s & 1];
#pragma unroll
        for (int kk = 0; kk < 32; kk += 8) {
            uint32_t a[2][4];
#pragma unroll
            for (int rt = 0; rt < 2; rt++) {
                int rb = wr * 32 + rt * 16;
                a[rt][0] = As[(rb + g) * 36 + kk + tg];
                a[rt][1] = As[(rb + g + 8) * 36 + kk + tg];
                a[rt][2] = As[(rb + g) * 36 + kk + tg + 4];
                a[rt][3] = As[(rb + g + 8) * 36 + kk + tg + 4];
            }
#pragma unroll
            for (int ct = 0; ct < NT; ct++) {
                int nb = wc * (DOUT / 2) + ct * 8 + g;
                uint32_t b0 = Ws[(kk + tg) * WST + nb];
                uint32_t b1 = Ws[(kk + tg + 4) * WST + nb];
                mma_tf32(acc[0][ct], a[0], b0, b1);
                mma_tf32(acc[1][ct], a[1], b0, b1);
            }
        }
    }

#pragma unroll
    for (int rt = 0; rt < 2; rt++) {
        int gr = row0 + wr * 32 + rt * 16 + g;
#pragma unroll
        for (int ct = 0; ct < NT; ct++) {
            int nb = wc * (DOUT / 2) + ct * 8 + 2 * tg;
            float b0 = bias[nb], b1 = bias[nb + 1];
            if (gr < nrows)
                *(float2*)&out[(size_t)gr * DOUT + nb] =
                    make_float2(acc[rt][ct][0] + b0, acc[rt][ct][1] + b1);
            if (gr + 8 < nrows)
                *(float2*)&out[(size_t)(gr + 8) * DOUT + nb] =
                    make_float2(acc[rt][ct][2] + b0, acc[rt][ct][3] + b1);
        }
    }
}

// ---------------- column stats ----------------
__global__ void col_stats(const float* __restrict__ h, float* __restrict__ stats, int n) {
    __shared__ float red[512];
    int tid = threadIdx.x;
    int col = tid & 127, rh = tid >> 7;
    float s = 0.f, q = 0.f;
    for (int r = blockIdx.x * 2 + rh; r < n; r += gridDim.x * 2) {
        float v = h[(size_t)r * 128 + col];
        s += v; q += v * v;
    }
    red[tid] = s; red[256 + tid] = q;
    __syncthreads();
    if (tid < 128) {
        s = red[tid] + red[tid + 128];
        q = red[256 + tid] + red[256 + tid + 128];
        atomicAdd(&stats[tid], s);
        atomicAdd(&stats[DK + tid], q);
    }
}

// ---------------- BN finalize ----------------
__global__ void finalize_kernel(const float* __restrict__ stats,
                                const float* __restrict__ g,
                                const float* __restrict__ be,
                                float* __restrict__ ss, float invn) {
    int c = threadIdx.x;
    if (c < DK) {
        float mu  = stats[c] * invn;
        float var = stats[DK + c] * invn - mu * mu;
        float rs  = rsqrtf(var + BN_EPS);
        float s   = g[c] * rs;
        ss[c]      = s;
        ss[DK + c] = be[c] - mu * s;
    }
}

// ---------------- BN apply + exact GELU ----------------
__device__ __forceinline__ float gelu_exact(float v) {
    return 0.5f * v * (1.0f + erff(v * 0.70710678118654752f));
}

__global__ void bn_gelu_kernel(const float* __restrict__ h,
                               const float* __restrict__ ss,
                               float* __restrict__ out, int n4) {
    int i = blockIdx.x * blockDim.x + threadIdx.x;
    if (i >= n4) return;
    int c4 = i & (DK / 4 - 1);
    float4 v  = ((const float4*)h)[i];
    float4 sc = ((const float4*)ss)[c4];
    float4 sh = ((const float4*)(ss + DK))[c4];
    v.x = gelu_exact(v.x * sc.x + sh.x);
    v.y = gelu_exact(v.y * sc.y + sh.y);
    v.z = gelu_exact(v.z * sc.z + sh.z);
    v.w = gelu_exact(v.w * sc.w + sh.w);
    ((float4*)out)[i] = v;
}

// ---------------- launch ----------------
extern "C" void kernel_launch(void* const* d_in, const int* in_sizes, int n_in,
                              void* d_out, int out_size) {
    const float* x   = (const float*)d_in[0];
    const void*  ei  = d_in[1];
    const float* W0l = (const float*)d_in[2];
    const float* W0r = (const float*)d_in[3];
    const float* b0  = (const float*)d_in[4];
    const float* g0  = (const float*)d_in[5];
    const float* be0 = (const float*)d_in[6];
    const float* W1l = (const float*)d_in[7];
    const float* W1r = (const float*)d_in[8];
    const float* b1  = (const float*)d_in[9];
    const float* g1  = (const float*)d_in[10];
    const float* be1 = (const float*)d_in[11];
    const float* W2l = (const float*)d_in[12];
    const float* W2r = (const float*)d_in[13];
    const float* b2  = (const float*)d_in[14];
    float* out = (float*)d_out;

    int E = in_sizes[1] / 2;
    if (E > E_MAX) E = E_MAX;

    void* p;
    cudaGetSymbolAddress(&p, g_agg);   float* agg   = (float*)p;
    cudaGetSymbolAddress(&p, g_h);     float* h     = (float*)p;
    cudaGetSymbolAddress(&p, g_x1);    float* x1    = (float*)p;
    cudaGetSymbolAddress(&p, g_stats); float* stats = (float*)p;
    cudaGetSymbolAddress(&p, g_ss);    float* ss    = (float*)p;
    cudaGetSymbolAddress(&p, g_deg);   int*   deg   = (int*)p;

    const int smemA = 2 * (128 * 36 + 32 * (DK + 8)) * 4;
    const int smemB = 2 * (128 * 36 + 32 * (DOUT2 + 8)) * 4;
    cudaFuncSetAttribute(gemm_mma<DK>,    cudaFuncAttributeMaxDynamicSharedMemorySize, smemA);
    cudaFuncSetAttribute(gemm_mma<DOUT2>, cudaFuncAttributeMaxDynamicSharedMemorySize, smemB);

    int eb      = (E + 255) / 256;
    int gblocks = (N_NODES + 127) / 128;
    int gab     = (N_NODES * 32 + 255) / 256;
    int n4      = N_NODES * DK / 4;
    int bgb     = (n4 + 255) / 256;
    float invn  = 1.0f / (float)N_NODES;

    // ---- CSR build (once; reused by all 3 layers) ----
    detect_kernel<<<1, 128>>>((const int*)ei);
    zero_int_kernel<<<(N_NODES + 255) / 256, 256>>>(deg, N_NODES);
    hist_kernel<<<eb, 256>>>(ei, E);
    block_reduce_kernel<<<SCAN_G, SCAN_B>>>();
    scan_partials_kernel<<<1, 64>>>();
    block_scan_kernel<<<SCAN_G, SCAN_B>>>();
    fill_kernel<<<eb, 256>>>(ei, E);

    // ---- layer 0 ----
    zero_kernel<<<1, 64>>>((float4*)stats, 2 * DK / 4);
    gather_kernel<<<gab, 256>>>(x, agg);
    gemm_mma<DK><<<gblocks, 256, smemA>>>(agg, x, W0l, W0r, b0, h, N_NODES);
    col_stats<<<256, 256>>>(h, stats, N_NODES);
    finalize_kernel<<<1, 128>>>(stats, g0, be0, ss, invn);
    bn_gelu_kernel<<<bgb, 256>>>(h, ss, x1, n4);

    // ---- layer 1 ----
    zero_kernel<<<1, 64>>>((float4*)stats, 2 * DK / 4);
    gather_kernel<<<gab, 256>>>(x1, agg);
    gemm_mma<DK><<<gblocks, 256, smemA>>>(agg, x1, W1l, W1r, b1, h, N_NODES);
    col_stats<<<256, 256>>>(h, stats, N_NODES);
    finalize_kernel<<<1, 128>>>(stats, g1, be1, ss, invn);
    bn_gelu_kernel<<<bgb, 256>>>(h, ss, x1, n4);

    // ---- layer 2 (no BN/GELU) ----
    gather_kernel<<<gab, 256>>>(x1, agg);
    gemm_mma<DOUT2><<<gblocks, 256, smemB>>>(agg, x1, W2l, W2r, b2, out, N_NODES);
}

// round 6
// speedup vs baseline: 3.3254x; 1.1472x over previous
#include <cuda_runtime.h>
#include <math.h>
#include <stdint.h>

#define N_NODES 50000
#define E_MAX   1000000
#define DK 128
#define DOUT2 64
#define BN_EPS 1e-5f
#define SCAN_B 1024
#define SCAN_G ((N_NODES + SCAN_B - 1) / SCAN_B)   // 49

// ---------------- scratch ----------------
__device__ float g_agg[N_NODES * DK];   // also reused as y for layer 2
__device__ float g_h[N_NODES * DK];
__device__ float g_x1[N_NODES * DK];
__device__ float g_stats0[2 * DK];
__device__ float g_stats1[2 * DK];
__device__ int   g_is64;
__device__ int   g_deg[N_NODES];
__device__ int   g_rowptr[N_NODES + 1];
__device__ int   g_cur[N_NODES];
__device__ int   g_eidx[E_MAX];
__device__ int   g_part[SCAN_G];
__device__ int   g_partoff[SCAN_G + 1];

// ---------------- helpers ----------------
__device__ __forceinline__ uint32_t f2tf(float f) {
    uint32_t r; asm("cvt.rna.tf32.f32 %0, %1;" : "=r"(r) : "f"(f)); return r;
}
__device__ __forceinline__ void mma_tf32(float* c, const uint32_t* a,
                                         uint32_t b0, uint32_t b1) {
    asm volatile(
        "mma.sync.aligned.m16n8k8.row.col.f32.tf32.tf32.f32 "
        "{%0,%1,%2,%3}, {%4,%5,%6,%7}, {%8,%9}, {%0,%1,%2,%3};"
        : "+f"(c[0]), "+f"(c[1]), "+f"(c[2]), "+f"(c[3])
        : "r"(a[0]), "r"(a[1]), "r"(a[2]), "r"(a[3]), "r"(b0), "r"(b1));
}

// ---------------- init: zero deg + zero stats + detect dtype ----------------
__global__ void init_kernel(const int* __restrict__ ei32) {
    int idx = blockIdx.x * blockDim.x + threadIdx.x;
    if (idx < N_NODES) g_deg[idx] = 0;
    if (blockIdx.x == 0) {
        g_stats0[threadIdx.x] = 0.f;
        g_stats1[threadIdx.x] = 0.f;
    }
    if (blockIdx.x == 1) {
        __shared__ int any;
        if (threadIdx.x == 0) any = 0;
        __syncthreads();
        if (threadIdx.x < 128) {
            int w = 1 + 2 * threadIdx.x;
            if (ei32[w] != 0) atomicOr(&any, 1);
        }
        __syncthreads();
        if (threadIdx.x == 0) g_is64 = (any == 0) ? 1 : 0;
    }
}

// ---------------- CSR build ----------------
__global__ void hist_kernel(const void* __restrict__ eiv, int E) {
    int i = blockIdx.x * blockDim.x + threadIdx.x;
    if (i >= E) return;
    long long d;
    if (g_is64) d = ((const long long*)eiv)[E + i];
    else        d = ((const int*)eiv)[E + i];
    if ((unsigned long long)d < N_NODES) atomicAdd(&g_deg[(int)d], 1);
}

__global__ void block_reduce_kernel() {
    __shared__ int sm[32];
    int idx = blockIdx.x * SCAN_B + threadIdx.x;
    int v = (idx < N_NODES) ? g_deg[idx] : 0;
#pragma unroll
    for (int o = 16; o > 0; o >>= 1) v += __shfl_down_sync(0xffffffffu, v, o);
    if ((threadIdx.x & 31) == 0) sm[threadIdx.x >> 5] = v;
    __syncthreads();
    if (threadIdx.x < 32) {
        int w = sm[threadIdx.x];
#pragma unroll
        for (int o = 16; o > 0; o >>= 1) w += __shfl_down_sync(0xffffffffu, w, o);
        if (threadIdx.x == 0) g_part[blockIdx.x] = w;
    }
}

__global__ void scan_partials_kernel() {
    __shared__ int sm[SCAN_G + 1];
    int t = threadIdx.x;
    if (t == 0) {
        int acc = 0;
        for (int i = 0; i < SCAN_G; i++) { sm[i] = acc; acc += g_part[i]; }
        sm[SCAN_G] = acc;
    }
    __syncthreads();
    if (t <= SCAN_G) g_partoff[t] = sm[t];
}

__global__ void block_scan_kernel() {
    __shared__ int warp_sums[32];
    int idx = blockIdx.x * SCAN_B + threadIdx.x;
    int lane = threadIdx.x & 31, warp = threadIdx.x >> 5;
    int v = (idx < N_NODES) ? g_deg[idx] : 0;
    int s = v;
#pragma unroll
    for (int o = 1; o < 32; o <<= 1) {
        int u = __shfl_up_sync(0xffffffffu, s, o);
        if (lane >= o) s += u;
    }
    if (lane == 31) warp_sums[warp] = s;
    __syncthreads();
    if (warp == 0) {
        int w = warp_sums[lane];
        int ws = w;
#pragma unroll
        for (int o = 1; o < 32; o <<= 1) {
            int u = __shfl_up_sync(0xffffffffu, ws, o);
            if (lane >= o) ws += u;
        }
        warp_sums[lane] = ws - w;
    }
    __syncthreads();
    int excl = s - v + warp_sums[warp] + g_partoff[blockIdx.x];
    if (idx < N_NODES) {
        g_rowptr[idx] = excl;
        g_cur[idx]    = excl;
        if (idx == N_NODES - 1) g_rowptr[N_NODES] = excl + v;
    }
}

__global__ void fill_kernel(const void* __restrict__ eiv, int E) {
    int i = blockIdx.x * blockDim.x + threadIdx.x;
    if (i >= E) return;
    long long s, d;
    if (g_is64) {
        s = ((const long long*)eiv)[i];
        d = ((const long long*)eiv)[E + i];
    } else {
        s = ((const int*)eiv)[i];
        d = ((const int*)eiv)[E + i];
    }
    if ((unsigned long long)s >= N_NODES || (unsigned long long)d >= N_NODES) return;
    int pos = atomicAdd(&g_cur[(int)d], 1);
    g_eidx[pos] = (int)s;
}

// ---------------- gather (128-wide): agg[n] = sum x[eidx[e]] ----------------
__global__ void __launch_bounds__(256)
gather_kernel(const float* __restrict__ x, float* __restrict__ agg) {
    int node = (blockIdx.x * blockDim.x + threadIdx.x) >> 5;
    int lane = threadIdx.x & 31;
    if (node >= N_NODES) return;
    int beg = g_rowptr[node];
    int end = g_rowptr[node + 1];

    float4 a0 = make_float4(0.f, 0.f, 0.f, 0.f);
    float4 a1 = make_float4(0.f, 0.f, 0.f, 0.f);

    for (int base = beg; base < end; base += 32) {
        int n = end - base; if (n > 32) n = 32;
        int myidx = (base + lane < end) ? g_eidx[base + lane] : 0;
        int j = 0;
        for (; j + 3 < n; j += 4) {
            int s0 = __shfl_sync(0xffffffffu, myidx, j);
            int s1 = __shfl_sync(0xffffffffu, myidx, j + 1);
            int s2 = __shfl_sync(0xffffffffu, myidx, j + 2);
            int s3 = __shfl_sync(0xffffffffu, myidx, j + 3);
            float4 v0 = *(const float4*)(x + (size_t)s0 * DK + lane * 4);
            float4 v1 = *(const float4*)(x + (size_t)s1 * DK + lane * 4);
            float4 v2 = *(const float4*)(x + (size_t)s2 * DK + lane * 4);
            float4 v3 = *(const float4*)(x + (size_t)s3 * DK + lane * 4);
            a0.x += v0.x; a0.y += v0.y; a0.z += v0.z; a0.w += v0.w;
            a1.x += v1.x; a1.y += v1.y; a1.z += v1.z; a1.w += v1.w;
            a0.x += v2.x; a0.y += v2.y; a0.z += v2.z; a0.w += v2.w;
            a1.x += v3.x; a1.y += v3.y; a1.z += v3.z; a1.w += v3.w;
        }
        for (; j < n; j++) {
            int s0 = __shfl_sync(0xffffffffu, myidx, j);
            float4 v0 = *(const float4*)(x + (size_t)s0 * DK + lane * 4);
            a0.x += v0.x; a0.y += v0.y; a0.z += v0.z; a0.w += v0.w;
        }
    }
    a0.x += a1.x; a0.y += a1.y; a0.z += a1.z; a0.w += a1.w;
    *(float4*)(agg + (size_t)node * DK + lane * 4) = a0;
}

// ---------------- gather (64-wide) + accumulate into out ----------------
__global__ void __launch_bounds__(256)
gather64_add_kernel(const float* __restrict__ y, float* __restrict__ out) {
    int node = (blockIdx.x * blockDim.x + threadIdx.x) >> 5;
    int lane = threadIdx.x & 31;
    if (node >= N_NODES) return;
    int beg = g_rowptr[node];
    int end = g_rowptr[node + 1];

    float2 a0 = make_float2(0.f, 0.f);
    float2 a1 = make_float2(0.f, 0.f);

    for (int base = beg; base < end; base += 32) {
        int n = end - base; if (n > 32) n = 32;
        int myidx = (base + lane < end) ? g_eidx[base + lane] : 0;
        int j = 0;
        for (; j + 3 < n; j += 4) {
            int s0 = __shfl_sync(0xffffffffu, myidx, j);
            int s1 = __shfl_sync(0xffffffffu, myidx, j + 1);
            int s2 = __shfl_sync(0xffffffffu, myidx, j + 2);
            int s3 = __shfl_sync(0xffffffffu, myidx, j + 3);
            float2 v0 = *(const float2*)(y + (size_t)s0 * DOUT2 + lane * 2);
            float2 v1 = *(const float2*)(y + (size_t)s1 * DOUT2 + lane * 2);
            float2 v2 = *(const float2*)(y + (size_t)s2 * DOUT2 + lane * 2);
            float2 v3 = *(const float2*)(y + (size_t)s3 * DOUT2 + lane * 2);
            a0.x += v0.x; a0.y += v0.y; a1.x += v1.x; a1.y += v1.y;
            a0.x += v2.x; a0.y += v2.y; a1.x += v3.x; a1.y += v3.y;
        }
        for (; j < n; j++) {
            int s0 = __shfl_sync(0xffffffffu, myidx, j);
            float2 v0 = *(const float2*)(y + (size_t)s0 * DOUT2 + lane * 2);
            a0.x += v0.x; a0.y += v0.y;
        }
    }
    a0.x += a1.x; a0.y += a1.y;
    float2* po = (float2*)(out + (size_t)node * DOUT2 + lane * 2);
    float2 o = *po;
    o.x += a0.x; o.y += a0.y;
    *po = o;
}

// ---------------- mma.sync tf32 GEMM ----------------
// PHASES=2: out = A@Wl + X@Wr + b  (dual K-phase)
// PHASES=1 + SPLIT: cols 0-63 -> y = A@Wl (no bias); cols 64-127 -> out = A@Wr + b
// STATS: column sum/sumsq of the (bias-added) result accumulated into stats.

template<int DOUT>
struct StageRegs {
    float4 rv[4];
    float4 wv[DOUT == 128 ? 4 : 2];
};

template<int DOUT, bool SPLIT>
__device__ __forceinline__ void ldg_stage(StageRegs<DOUT>& R,
                                          const float* __restrict__ rows,
                                          const float* __restrict__ Wl,
                                          const float* __restrict__ Wr,
                                          int k0, int row0, int nrows, int tid) {
#pragma unroll
    for (int j = 0; j < 4; j++) {
        int idx = tid + j * 256;
        int r = idx >> 3, c4 = idx & 7;
        float4 v = make_float4(0.f, 0.f, 0.f, 0.f);
        if (row0 + r < nrows)
            v = *(const float4*)&rows[(size_t)(row0 + r) * 128 + k0 + c4 * 4];
        R.rv[j] = v;
    }
    constexpr int WI = (DOUT == 128) ? 4 : 2;
#pragma unroll
    for (int j = 0; j < WI; j++) {
        int idx = tid + j * 256;
        int k, c4;
        if (DOUT == 128) { k = idx >> 5; c4 = idx & 31; }
        else             { k = idx >> 4; c4 = idx & 15; }
        if (SPLIT) {
            int c = c4 * 4;
            if (c < 64) R.wv[j] = *(const float4*)&Wl[(size_t)(k0 + k) * 64 + c];
            else        R.wv[j] = *(const float4*)&Wr[(size_t)(k0 + k) * 64 + (c - 64)];
        } else {
            R.wv[j] = *(const float4*)&Wl[(size_t)(k0 + k) * DOUT + c4 * 4];
        }
    }
}

template<int DOUT>
__device__ __forceinline__ void sts_stage(const StageRegs<DOUT>& R,
                                          uint32_t* sA, uint32_t* sW, int tid) {
    constexpr int WST = DOUT + 8;
#pragma unroll
    for (int j = 0; j < 4; j++) {
        int idx = tid + j * 256;
        int r = idx >> 3, c4 = idx & 7;
        float4 v = R.rv[j];
        *(uint4*)&sA[r * 36 + c4 * 4] =
            make_uint4(f2tf(v.x), f2tf(v.y), f2tf(v.z), f2tf(v.w));
    }
    constexpr int WI = (DOUT == 128) ? 4 : 2;
#pragma unroll
    for (int j = 0; j < WI; j++) {
        int idx = tid + j * 256;
        int k, c4;
        if (DOUT == 128) { k = idx >> 5; c4 = idx & 31; }
        else             { k = idx >> 4; c4 = idx & 15; }
        float4 v = R.wv[j];
        *(uint4*)&sW[k * WST + c4 * 4] =
            make_uint4(f2tf(v.x), f2tf(v.y), f2tf(v.z), f2tf(v.w));
    }
}

template<int DOUT, int PHASES, bool STATS, bool SPLIT>
__global__ void __launch_bounds__(256, 1)
gemm_mma(const float* __restrict__ A, const float* __restrict__ X,
         const float* __restrict__ Wl, const float* __restrict__ Wr,
         const float* __restrict__ bias, float* __restrict__ out,
         float* __restrict__ y, float* __restrict__ stats, int nrows) {
    constexpr int WST    = DOUT + 8;
    constexpr int NT     = DOUT / 16;
    constexpr int ASZ    = 128 * 36;
    constexpr int NSTAGE = PHASES * 4;

    extern __shared__ uint32_t sm[];
    uint32_t* sA[2] = { sm, sm + ASZ };
    uint32_t* sW[2] = { sm + 2 * ASZ, sm + 2 * ASZ + 32 * WST };

    int tid  = threadIdx.x;
    int wid  = tid >> 5, lane = tid & 31;
    int wr   = wid & 3, wc = wid >> 2;
    int g    = lane >> 2, tg = lane & 3;
    int row0 = blockIdx.x * 128;

    float acc[2][NT][4];
#pragma unroll
    for (int rt = 0; rt < 2; rt++)
#pragma unroll
        for (int ct = 0; ct < NT; ct++)
#pragma unroll
            for (int j = 0; j < 4; j++) acc[rt][ct][j] = 0.f;

    StageRegs<DOUT> R;
    ldg_stage<DOUT, SPLIT>(R, A, Wl, Wr, 0, row0, nrows, tid);
    sts_stage<DOUT>(R, sA[0], sW[0], tid);

#pragma unroll
    for (int s = 0; s < NSTAGE; s++) {
        if (s + 1 < NSTAGE) {
            const float* rows = (PHASES == 2 && s + 1 >= 4) ? X : A;
            const float* W1   = (PHASES == 2 && s + 1 >= 4) ? Wr : Wl;
            ldg_stage<DOUT, SPLIT>(R, rows, W1, Wr, ((s + 1) & 3) * 32, row0, nrows, tid);
        }
        __syncthreads();
        if (s + 1 < NSTAGE) sts_stage<DOUT>(R, sA[(s + 1) & 1], sW[(s + 1) & 1], tid);

        const uint32_t* As = sA[s & 1];
        const uint32_t* Ws = sW[s & 1];
#pragma unroll
        for (int kk = 0; kk < 32; kk += 8) {
            uint32_t a[2][4];
#pragma unroll
            for (int rt = 0; rt < 2; rt++) {
                int rb = wr * 32 + rt * 16;
                a[rt][0] = As[(rb + g) * 36 + kk + tg];
                a[rt][1] = As[(rb + g + 8) * 36 + kk + tg];
                a[rt][2] = As[(rb + g) * 36 + kk + tg + 4];
                a[rt][3] = As[(rb + g + 8) * 36 + kk + tg + 4];
            }
#pragma unroll
            for (int ct = 0; ct < NT; ct++) {
                int nb = wc * (DOUT / 2) + ct * 8 + g;
                uint32_t b0 = Ws[(kk + tg) * WST + nb];
                uint32_t b1 = Ws[(kk + tg + 4) * WST + nb];
                mma_tf32(acc[0][ct], a[0], b0, b1);
                mma_tf32(acc[1][ct], a[1], b0, b1);
            }
        }
    }

    // ---- epilogue ----
    float* sst = (float*)sm;
    if (STATS) {
        __syncthreads();
        sst[tid] = 0.f;
        __syncthreads();
    }

#pragma unroll
    for (int ct = 0; ct < NT; ct++) {
        int nb = wc * (DOUT / 2) + ct * 8 + 2 * tg;
        float b0, b1;
        if (SPLIT) {
            b0 = (nb >= 64) ? bias[nb - 64] : 0.f;
            b1 = (nb >= 64) ? bias[nb - 63] : 0.f;
        } else {
            b0 = bias[nb]; b1 = bias[nb + 1];
        }
        float s0 = 0.f, q0 = 0.f, s1 = 0.f, q1 = 0.f;
#pragma unroll
        for (int rt = 0; rt < 2; rt++) {
            int gr = row0 + wr * 32 + rt * 16 + g;
            float v0 = acc[rt][ct][0] + b0, v1 = acc[rt][ct][1] + b1;
            float v2 = acc[rt][ct][2] + b0, v3 = acc[rt][ct][3] + b1;
            if (gr < nrows) {
                float* dst;
                if (SPLIT) dst = (nb < 64) ? (y + (size_t)gr * 64 + nb)
                                           : (out + (size_t)gr * 64 + nb - 64);
                else       dst = out + (size_t)gr * DOUT + nb;
                *(float2*)dst = make_float2(v0, v1);
                if (STATS) { s0 += v0; q0 += v0 * v0; s1 += v1; q1 += v1 * v1; }
            }
            if (gr + 8 < nrows) {
                float* dst;
                if (SPLIT) dst = (nb < 64) ? (y + (size_t)(gr + 8) * 64 + nb)
                                           : (out + (size_t)(gr + 8) * 64 + nb - 64);
                else       dst = out + (size_t)(gr + 8) * DOUT + nb;
                *(float2*)dst = make_float2(v2, v3);
                if (STATS) { s0 += v2; q0 += v2 * v2; s1 += v3; q1 += v3 * v3; }
            }
        }
        if (STATS) {
            // reduce over g (lane bits 2..4)
#pragma unroll
            for (int off = 4; off <= 16; off <<= 1) {
                s0 += __shfl_xor_sync(0xffffffffu, s0, off);
                q0 += __shfl_xor_sync(0xffffffffu, q0, off);
                s1 += __shfl_xor_sync(0xffffffffu, s1, off);
                q1 += __shfl_xor_sync(0xffffffffu, q1, off);
            }
            if (g == 0) {
                atomicAdd(&sst[nb],           s0);
                atomicAdd(&sst[DOUT + nb],    q0);
                atomicAdd(&sst[nb + 1],       s1);
                atomicAdd(&sst[DOUT + nb + 1],q1);
            }
        }
    }

    if (STATS) {
        __syncthreads();
        atomicAdd(&stats[tid], sst[tid]);   // tid < 256 == 2*DOUT
    }
}

// ---------------- BN (finalize fused) + exact GELU ----------------
__device__ __forceinline__ float gelu_exact(float v) {
    return 0.5f * v * (1.0f + erff(v * 0.70710678118654752f));
}

__global__ void bn_gelu_kernel(const float* __restrict__ h,
                               const float* __restrict__ stats,
                               const float* __restrict__ g,
                               const float* __restrict__ be,
                               float* __restrict__ out, int n4, float invn) {
    __shared__ float ssm[2 * DK];
    int t = threadIdx.x;
    if (t < DK) {
        float mu  = stats[t] * invn;
        float var = stats[DK + t] * invn - mu * mu;
        float rs  = rsqrtf(var + BN_EPS);
        float s   = g[t] * rs;
        ssm[t]      = s;
        ssm[DK + t] = be[t] - mu * s;
    }
    __syncthreads();
    int i = blockIdx.x * blockDim.x + t;
    if (i >= n4) return;
    int c4 = i & (DK / 4 - 1);
    float4 v  = ((const float4*)h)[i];
    float4 sc = *(float4*)&ssm[c4 * 4];
    float4 sh = *(float4*)&ssm[DK + c4 * 4];
    v.x = gelu_exact(v.x * sc.x + sh.x);
    v.y = gelu_exact(v.y * sc.y + sh.y);
    v.z = gelu_exact(v.z * sc.z + sh.z);
    v.w = gelu_exact(v.w * sc.w + sh.w);
    ((float4*)out)[i] = v;
}

// ---------------- launch ----------------
extern "C" void kernel_launch(void* const* d_in, const int* in_sizes, int n_in,
                              void* d_out, int out_size) {
    const float* x   = (const float*)d_in[0];
    const void*  ei  = d_in[1];
    const float* W0l = (const float*)d_in[2];
    const float* W0r = (const float*)d_in[3];
    const float* b0  = (const float*)d_in[4];
    const float* g0  = (const float*)d_in[5];
    const float* be0 = (const float*)d_in[6];
    const float* W1l = (const float*)d_in[7];
    const float* W1r = (const float*)d_in[8];
    const float* b1  = (const float*)d_in[9];
    const float* g1  = (const float*)d_in[10];
    const float* be1 = (const float*)d_in[11];
    const float* W2l = (const float*)d_in[12];
    const float* W2r = (const float*)d_in[13];
    const float* b2  = (const float*)d_in[14];
    float* out = (float*)d_out;

    int E = in_sizes[1] / 2;
    if (E > E_MAX) E = E_MAX;

    void* p;
    cudaGetSymbolAddress(&p, g_agg);    float* agg    = (float*)p;
    cudaGetSymbolAddress(&p, g_h);      float* h      = (float*)p;
    cudaGetSymbolAddress(&p, g_x1);     float* x1     = (float*)p;
    cudaGetSymbolAddress(&p, g_stats0); float* stats0 = (float*)p;
    cudaGetSymbolAddress(&p, g_stats1); float* stats1 = (float*)p;

    const int smemA = 2 * (128 * 36 + 32 * (128 + 8)) * 4;   // 71680
    cudaFuncSetAttribute((const void*)gemm_mma<DK, 2, true,  false>,
                         cudaFuncAttributeMaxDynamicSharedMemorySize, smemA);
    cudaFuncSetAttribute((const void*)gemm_mma<DK, 1, false, true>,
                         cudaFuncAttributeMaxDynamicSharedMemorySize, smemA);

    int eb      = (E + 255) / 256;
    int gblocks = (N_NODES + 127) / 128;
    int gab     = (N_NODES * 32 + 255) / 256;
    int n4      = N_NODES * DK / 4;
    int bgb     = (n4 + 255) / 256;
    float invn  = 1.0f / (float)N_NODES;

    // ---- CSR build (once) ----
    init_kernel<<<(N_NODES + 255) / 256, 256>>>((const int*)ei);
    hist_kernel<<<eb, 256>>>(ei, E);
    block_reduce_kernel<<<SCAN_G, SCAN_B>>>();
    scan_partials_kernel<<<1, 64>>>();
    block_scan_kernel<<<SCAN_G, SCAN_B>>>();
    fill_kernel<<<eb, 256>>>(ei, E);

    // ---- layer 0 ----
    gather_kernel<<<gab, 256>>>(x, agg);
    gemm_mma<DK, 2, true, false><<<gblocks, 256, smemA>>>(
        agg, x, W0l, W0r, b0, h, nullptr, stats0, N_NODES);
    bn_gelu_kernel<<<bgb, 256>>>(h, stats0, g0, be0, x1, n4, invn);

    // ---- layer 1 ----
    gather_kernel<<<gab, 256>>>(x1, agg);
    gemm_mma<DK, 2, true, false><<<gblocks, 256, smemA>>>(
        agg, x1, W1l, W1r, b1, h, nullptr, stats1, N_NODES);
    bn_gelu_kernel<<<bgb, 256>>>(h, stats1, g1, be1, x1, n4, invn);

    // ---- layer 2: gemm first ([y | self+bias]), then 64-wide gather-add ----
    gemm_mma<DK, 1, false, true><<<gblocks, 256, smemA>>>(
        x1, x1, W2l, W2r, b2, out, agg, nullptr, N_NODES);
    gather64_add_kernel<<<gab, 256>>>(agg, out);
}